// round 6
// baseline (speedup 1.0000x reference)
#include <cuda_runtime.h>
#include <math.h>

// QLSTM: seq=2048, batch=64, in=512, hid=512
// Fused persistent kernel: one CTA per (batch-half, 8-hidden-column group),
// grid-wide software barrier per timestep. All math fp32.

#define SEQ    2048
#define BATCH  64
#define HID    512
#define KTOT   1024           // in + hid
#define NCTA   128            // 2 batch halves x 64 col groups
#define ROWS   32             // batch rows per CTA
#define GCOLS  32             // gate-cols per CTA (4 gates x 8 j)
#define KC     128            // K chunk
#define NCHUNK 8              // KTOT / KC

// persistent state (static __device__ arrays are the sanctioned scratch path)
__device__ __align__(16) float g_hx[2][BATCH * HID];
__device__ int g_count;

__global__ void qlstm_init_kernel() {
    int i = blockIdx.x * blockDim.x + threadIdx.x;
    if (i < 2 * BATCH * HID) ((float*)g_hx)[i] = 0.0f;
    if (i == 0) g_count = 0;
}

__global__ __launch_bounds__(256, 1) void qlstm_kernel(
    const float* __restrict__ x,
    const float* __restrict__ Wf, const float* __restrict__ bf,
    const float* __restrict__ Wi, const float* __restrict__ bi,
    const float* __restrict__ Wg, const float* __restrict__ bg,
    const float* __restrict__ Wo, const float* __restrict__ bo,
    float* __restrict__ out)
{
    extern __shared__ float sm[];
    float* Ws = sm;                        // [KTOT][32]        = 32768 floats
    float* As = Ws + KTOT * GCOLS;         // 2 x [32][KC]      =  8192 floats
    float* Sg = As + 2 * ROWS * KC;        // [32][33]          =  1056 floats
    float* bs = Sg + 32 * 33;              // [32]

    const int tid = threadIdx.x;
    const int cg  = blockIdx.x;            // 0..63 : hidden col group (8 j's)
    const int bh  = blockIdx.y;            // 0..1  : batch half
    const int rb0 = bh * ROWS;

    // ---- one-time: load weight slice [1024 x 32] and bias slice into smem ----
    for (int idx = tid; idx < KTOT * GCOLS; idx += 256) {
        int k = idx >> 5, c = idx & 31;
        int g = c >> 3, j = cg * 8 + (c & 7);
        const float* w = (g == 0) ? Wf : (g == 1) ? Wi : (g == 2) ? Wg : Wo;
        Ws[idx] = w[k * HID + j];          // Ws[k*32 + c]
    }
    if (tid < GCOLS) {
        int g = tid >> 3, j = cg * 8 + (tid & 7);
        const float* bb = (g == 0) ? bf : (g == 1) ? bi : (g == 2) ? bg : bo;
        bs[tid] = bb[j];
    }
    __syncthreads();

    const int ty = tid >> 4, tx = tid & 15;     // GEMM micro-tile coords
    const int bl = tid >> 3, jj = tid & 7;      // epilogue cell coords
    const int b  = rb0 + bl;
    const int j  = cg * 8 + jj;

    float creg = 0.0f;                          // cx cell, register-resident

    for (int t = 0; t < SEQ; t++) {
        const float4* xbase = reinterpret_cast<const float4*>(x) +
                              (size_t)(t * BATCH + rb0) * (HID / 4);
        const float4* hbase = reinterpret_cast<const float4*>(g_hx[t & 1]) +
                              (size_t)rb0 * (HID / 4);

        // chunk loader: chunk c<4 from x_t, c>=4 from hx (L2-coherent loads)
        auto load_chunk = [&](int c, float4 r[4]) {
            if (c < 4) {
                #pragma unroll
                for (int s = 0; s < 4; s++) {
                    int e = tid + s * 256;
                    int row = e >> 5, kq = e & 31;
                    r[s] = __ldg(xbase + row * (HID / 4) + c * 32 + kq);
                }
            } else {
                #pragma unroll
                for (int s = 0; s < 4; s++) {
                    int e = tid + s * 256;
                    int row = e >> 5, kq = e & 31;
                    r[s] = __ldcg(hbase + row * (HID / 4) + (c - 4) * 32 + kq);
                }
            }
        };
        auto store_chunk = [&](int buf, const float4 r[4]) {
            float4* dst = reinterpret_cast<float4*>(As + buf * ROWS * KC);
            #pragma unroll
            for (int s = 0; s < 4; s++) {
                int e = tid + s * 256;
                int row = e >> 5, kq = e & 31;
                dst[row * 32 + kq] = r[s];
            }
        };

        float acc00 = 0.f, acc01 = 0.f, acc10 = 0.f, acc11 = 0.f;

        float4 r[4];
        load_chunk(0, r);
        store_chunk(0, r);
        __syncthreads();

        #pragma unroll 1
        for (int c = 0; c < NCHUNK; c++) {
            float4 rn[4];
            if (c + 1 < NCHUNK) load_chunk(c + 1, rn);

            const float4* A4 = reinterpret_cast<const float4*>(As + (c & 1) * ROWS * KC);
            const float*  wb = Ws + c * KC * GCOLS + 2 * tx;
            #pragma unroll
            for (int k4 = 0; k4 < KC / 4; k4++) {
                float4 a0 = A4[(2 * ty)     * 32 + k4];
                float4 a1 = A4[(2 * ty + 1) * 32 + k4];
                const float* wk = wb + k4 * 4 * 32;
                float2 w0 = *reinterpret_cast<const float2*>(wk);
                float2 w1 = *reinterpret_cast<const float2*>(wk + 32);
                float2 w2 = *reinterpret_cast<const float2*>(wk + 64);
                float2 w3 = *reinterpret_cast<const float2*>(wk + 96);
                acc00 += a0.x * w0.x; acc01 += a0.x * w0.y;
                acc10 += a1.x * w0.x; acc11 += a1.x * w0.y;
                acc00 += a0.y * w1.x; acc01 += a0.y * w1.y;
                acc10 += a1.y * w1.x; acc11 += a1.y * w1.y;
                acc00 += a0.z * w2.x; acc01 += a0.z * w2.y;
                acc10 += a1.z * w2.x; acc11 += a1.z * w2.y;
                acc00 += a0.w * w3.x; acc01 += a0.w * w3.y;
                acc10 += a1.w * w3.x; acc11 += a1.w * w3.y;
            }
            __syncthreads();
            if (c + 1 < NCHUNK) {
                store_chunk((c + 1) & 1, rn);
                __syncthreads();
            }
        }

        // stage gate pre-activations to smem (padded to kill bank conflicts)
        Sg[(2 * tx)     * 33 + 2 * ty]     = acc00;
        Sg[(2 * tx + 1) * 33 + 2 * ty]     = acc01;
        Sg[(2 * tx)     * 33 + 2 * ty + 1] = acc10;
        Sg[(2 * tx + 1) * 33 + 2 * ty + 1] = acc11;
        __syncthreads();

        // elementwise LSTM cell update: one (b, j) cell per thread
        float pf = Sg[(jj)      * 33 + bl] + bs[jj];
        float pi = Sg[(8 + jj)  * 33 + bl] + bs[8 + jj];
        float pg = Sg[(16 + jj) * 33 + bl] + bs[16 + jj];
        float po = Sg[(24 + jj) * 33 + bl] + bs[24 + jj];
        float fgate = 1.0f / (1.0f + expf(-pf));
        float igate = 1.0f / (1.0f + expf(-pi));
        float ggate = tanhf(pg);
        float ogate = 1.0f / (1.0f + expf(-po));
        creg = fgate * creg + igate * ggate;
        float h = ogate * tanhf(creg);

        out[((size_t)t * BATCH + b) * HID + j] = h;
        __stcg(&g_hx[(t + 1) & 1][b * HID + j], h);
        if (t == SEQ - 1) {
            size_t base = (size_t)SEQ * BATCH * HID;
            out[base + b * HID + j] = h;                   // final hx
            out[base + BATCH * HID + b * HID + j] = creg;  // final cx
        }

        // ---- grid-wide barrier ----
        __threadfence();
        __syncthreads();
        if (tid == 0) {
            atomicAdd(&g_count, 1);
            int target = NCTA * (t + 1);
            while (*(volatile int*)&g_count < target) { }
            __threadfence();
        }
        __syncthreads();
    }
}

extern "C" void kernel_launch(void* const* d_in, const int* in_sizes, int n_in,
                              void* d_out, int out_size) {
    (void)in_sizes; (void)n_in; (void)out_size;
    const float* x  = (const float*)d_in[0];
    const float* Wf = (const float*)d_in[1];
    const float* bf = (const float*)d_in[2];
    const float* Wi = (const float*)d_in[3];
    const float* bi = (const float*)d_in[4];
    const float* Wg = (const float*)d_in[5];
    const float* bg = (const float*)d_in[6];
    const float* Wo = (const float*)d_in[7];
    const float* bo = (const float*)d_in[8];
    float* out = (float*)d_out;

    qlstm_init_kernel<<<256, 256>>>();

    size_t smem_bytes = (size_t)(KTOT * GCOLS + 2 * ROWS * KC + 32 * 33 + 32) * sizeof(float);
    cudaFuncSetAttribute(qlstm_kernel,
                         cudaFuncAttributeMaxDynamicSharedMemorySize,
                         (int)smem_bytes);
    dim3 grid(64, 2);
    qlstm_kernel<<<grid, 256, smem_bytes>>>(x, Wf, bf, Wi, bi, Wg, bg, Wo, bo, out);
}